// round 7
// baseline (speedup 1.0000x reference)
#include <cuda_runtime.h>
#include <cuda_bf16.h>
#include <mma.h>
#include <cstdint>

using namespace nvcuda;

#define NB   4
#define CIN  512
#define COUT 64
#define SS   16384   // T*H*W
#define NSPLIT 32
#define MTOT 640     // 512 (add1) + 128 (occ1) fused rows

// ---------------- scratch (device globals; no allocs allowed) ----------------
__device__ float g_y1  [(size_t)NB * CIN * SS];   // relu(add1) fp32 (B,512,S)
__device__ float g_h1  [(size_t)NB * 128 * SS];   // relu(occ1)
__device__ float g_h2  [(size_t)NB *  64 * SS];
__device__ float g_occ [(size_t)NB *  64 * SS];
__device__ float g_P   [(size_t)NB * COUT * CIN];
__device__ float g_q   [(size_t)NB * COUT];
__device__ __nv_bfloat16 g_wch[MTOT * CIN];       // concat W rows, hi
__device__ __nv_bfloat16 g_wcl[MTOT * CIN];       // concat W rows, lo
__device__ float g_bc[MTOT];                      // concat bias

// ---------------- helpers ----------------------------------------------------
__device__ __forceinline__ uint32_t smem_u32(const void* p) {
    uint32_t a;
    asm("{ .reg .u64 t; cvta.to.shared.u64 t, %1; cvt.u32.u64 %0, t; }" : "=r"(a) : "l"(p));
    return a;
}
__device__ __forceinline__ void cp16(uint32_t dst, const void* src) {
    asm volatile("cp.async.cg.shared.global [%0], [%1], 16;" :: "r"(dst), "l"(src));
}
__device__ __forceinline__ void cp_commit() {
    asm volatile("cp.async.commit_group;" ::: "memory");
}
template<int N>
__device__ __forceinline__ void cp_wait() {
    asm volatile("cp.async.wait_group %0;" :: "n"(N) : "memory");
}

// ---------------- fused HMMA GEMM -------------------------------------------
// D(128m x 128n) = Wc(640,512) x X^T ; A bf16 hi/lo preconverted,
// B built in-kernel from fp32 x (B,512,S): SMEM stage + hi/lo split transpose.
// 3-term: Ahi*Bhi + Ahi*Blo + Alo*Bhi (fp32 accum). Epilogue: bias+relu,
// rows <512 -> y1 (B,512,S), rows >=512 -> h1 (B,128,S).
//
// NOTE (R6 post-mortem): cp.async.wait_group is PER-THREAD. Any consumer of
// another thread's cp.async data needs cp_wait + __syncthreads BEFORE reading.
//
// smem layout (bytes):
//   A  : 2 stages x (hi 10240 + lo 10240)           [     0 ..  40960)
//   X  : 2 stages x 32x132 fp32 (16896)             [ 40960 ..  74752)
//   B  : 2 stages x (hi 10240 + lo 10240)           [ 74752 .. 115712)
#define AOFF 0
#define XOFF 40960
#define BOFF 74752
#define HSMEM 115712
__global__ __launch_bounds__(256)
void fused_gemm(const __nv_bfloat16* __restrict__ Wh, const __nv_bfloat16* __restrict__ Wl,
                const float* __restrict__ X, const float* __restrict__ bias,
                float* __restrict__ Y1, float* __restrict__ H1)
{
    extern __shared__ __align__(128) char smem[];
    const int t = threadIdx.x, wid = t >> 5;
    const int n0 = blockIdx.x * 128, m0 = blockIdx.y * 128, b = blockIdx.z;
    const uint32_t sb = smem_u32(smem);

    const int wm = wid & 3;        // 4 warp rows -> 32 m each
    const int wn = wid >> 2;       // 2 warp cols -> 64 n each

    const __nv_bfloat16* wh = Wh + (long)m0 * 512;
    const __nv_bfloat16* wl = Wl + (long)m0 * 512;
    const float*         xb = X + (long)b * CIN * SS + n0;

    // issue cp.async for chunk c into stage st: A hi/lo tiles + X fp32 stage
    auto issue_chunk = [&](int c, int st) {
        const int k0 = c * 32;
#pragma unroll
        for (int i = 0; i < 4; ++i) {
            const int vid = t + i * 256;
            const int tile = vid >> 9;           // 0=hi 1=lo
            const int r    = (vid >> 2) & 127;
            const int v    = vid & 3;
            const __nv_bfloat16* src = (tile == 0 ? wh : wl) + (long)r * 512 + k0 + v * 8;
            cp16(sb + AOFF + st * 20480 + tile * 10240 + r * 80 + v * 16, src);
        }
#pragma unroll
        for (int i = 0; i < 4; ++i) {
            const int vid = t + i * 256;
            const int ci = vid >> 5;             // 0..31
            const int sg = vid & 31;             // 0..31 (x4 floats)
            cp16(sb + XOFF + st * 16896 + ci * 528 + sg * 16,
                 xb + (long)(k0 + ci) * SS + sg * 4);
        }
        cp_commit();
    };

    // convert X stage -> B hi/lo tiles (transpose + split)
    auto convert = [&](int st) {
        const int s  = t >> 1;                   // 0..127
        const int cg = (t & 1) * 16;             // 0 / 16
        const float* Xs = (const float*)(smem + XOFF + st * 16896);
        __nv_bfloat16* Bh = (__nv_bfloat16*)(smem + BOFF + st * 20480);
        __nv_bfloat16* Bl = Bh + 5120;
        union U8 { uint4 u[2]; __nv_bfloat16 h[16]; } uh, ul;
#pragma unroll
        for (int q = 0; q < 16; ++q) {
            float v = Xs[(cg + q) * 132 + s];
            __nv_bfloat16 h = __float2bfloat16(v);
            uh.h[q] = h;
            ul.h[q] = __float2bfloat16(v - __bfloat162float(h));
        }
        *(uint4*)(Bh + s * 40 + cg)     = uh.u[0];
        *(uint4*)(Bh + s * 40 + cg + 8) = uh.u[1];
        *(uint4*)(Bl + s * 40 + cg)     = ul.u[0];
        *(uint4*)(Bl + s * 40 + cg + 8) = ul.u[1];
    };

    wmma::fragment<wmma::accumulator, 16, 16, 16, float> acc[2][4];
#pragma unroll
    for (int i = 0; i < 2; ++i)
#pragma unroll
        for (int j = 0; j < 4; ++j) wmma::fill_fragment(acc[i][j], 0.0f);

    // prologue: chunk0+1 in flight; convert chunk0 AFTER wait+barrier
    issue_chunk(0, 0);
    issue_chunk(1, 1);
    cp_wait<1>();          // this thread's chunk-0 loads done
    __syncthreads();       // ALL threads' chunk-0 loads visible
    convert(0);
    __syncthreads();

    for (int c = 0; c < 16; ++c) {
        const int st = c & 1, nx = st ^ 1;
        const __nv_bfloat16* Ah  = (const __nv_bfloat16*)(smem + AOFF + st * 20480);
        const __nv_bfloat16* Al  = Ah + 5120;
        const __nv_bfloat16* Bhs = (const __nv_bfloat16*)(smem + BOFF + st * 20480);
        const __nv_bfloat16* Bls = Bhs + 5120;

#pragma unroll
        for (int kk = 0; kk < 32; kk += 16) {
            wmma::fragment<wmma::matrix_a, 16, 16, 16, __nv_bfloat16, wmma::row_major> fah[2], fal[2];
            wmma::fragment<wmma::matrix_b, 16, 16, 16, __nv_bfloat16, wmma::col_major> fbh[4], fbl[4];
#pragma unroll
            for (int i = 0; i < 2; ++i) {
                wmma::load_matrix_sync(fah[i], Ah + (wm * 32 + i * 16) * 40 + kk, 40);
                wmma::load_matrix_sync(fal[i], Al + (wm * 32 + i * 16) * 40 + kk, 40);
            }
#pragma unroll
            for (int j = 0; j < 4; ++j) {
                wmma::load_matrix_sync(fbh[j], Bhs + (wn * 64 + j * 16) * 40 + kk, 40);
                wmma::load_matrix_sync(fbl[j], Bls + (wn * 64 + j * 16) * 40 + kk, 40);
            }
#pragma unroll
            for (int i = 0; i < 2; ++i)
#pragma unroll
                for (int j = 0; j < 4; ++j) {
                    wmma::mma_sync(acc[i][j], fah[i], fbh[j], acc[i][j]);
                    wmma::mma_sync(acc[i][j], fah[i], fbl[j], acc[i][j]);
                    wmma::mma_sync(acc[i][j], fal[i], fbh[j], acc[i][j]);
                }
        }
        __syncthreads();                       // all stage-st smem reads done

        if (c + 2 < 16) { issue_chunk(c + 2, st); cp_wait<1>(); }
        else            { cp_wait<0>(); }
        if (c + 1 < 16) {
            __syncthreads();                   // chunk c+1 loads visible to all
            convert(nx);
        }
        __syncthreads();
    }

    // ---- epilogue: bias + relu, routed output ----
    float* Dsm = (float*)smem;    // [m][n] 128 x 132
#pragma unroll
    for (int i = 0; i < 2; ++i)
#pragma unroll
        for (int j = 0; j < 4; ++j)
            wmma::store_matrix_sync(Dsm + (wm * 32 + i * 16) * 132 + wn * 64 + j * 16,
                                    acc[i][j], 132, wmma::mem_row_major);
    __syncthreads();
    const int r  = t >> 1;
    const int cb = (t & 1) * 64;
    const float bv = bias[m0 + r];
    float* yr = (m0 < 512)
              ? Y1 + ((long)b * CIN + m0 + r) * SS + n0 + cb
              : H1 + ((long)b * 128 + (m0 - 512) + r) * SS + n0 + cb;
#pragma unroll
    for (int j = 0; j < 64; j += 4) {
        float4 v;
        v.x = fmaxf(Dsm[r * 132 + cb + j + 0] + bv, 0.f);
        v.y = fmaxf(Dsm[r * 132 + cb + j + 1] + bv, 0.f);
        v.z = fmaxf(Dsm[r * 132 + cb + j + 2] + bv, 0.f);
        v.w = fmaxf(Dsm[r * 132 + cb + j + 3] + bv, 0.f);
        *(float4*)(yr + j) = v;
    }
}

// ---------------- pre-passes --------------------------------------------------
__global__ void wsplit(const float* __restrict__ W,
                       __nv_bfloat16* __restrict__ H, __nv_bfloat16* __restrict__ L, int n)
{
    int i = blockIdx.x * 256 + threadIdx.x;
    if (i < n) {
        float v = W[i];
        __nv_bfloat16 h = __float2bfloat16(v);
        H[i] = h;
        L[i] = __float2bfloat16(v - __bfloat162float(h));
    }
}

__global__ void bconcat(const float* __restrict__ b1, const float* __restrict__ bo1,
                        float* __restrict__ bc)
{
    int i = blockIdx.x * 256 + threadIdx.x;
    if (i < 512) bc[i] = b1[i];
    else if (i < MTOT) bc[i] = bo1[i - 512];
}

// ---------------- small SIMT GEMM for occ2/occ3 -------------------------------
template<int BM, int BN, int BK, int TM, int TN, int ACT>
__global__ __launch_bounds__(256)
void gemm_bias_act(const float* __restrict__ X, const float* __restrict__ W,
                   const float* __restrict__ bias, float* __restrict__ Y,
                   int M, int K)
{
    const int S = SS;
    const int b = blockIdx.z;
    const float* Xb = X + (long)b * K * S;
    float*       Yb = Y + (long)b * M * S;
    const int n0 = blockIdx.x * BN;
    const int m0 = blockIdx.y * BM;

    __shared__ float Wsm[BK][BM + 4];
    __shared__ float Xsm[BK][BN + 4];

    const int t  = threadIdx.x;
    const int tn = t % (BN / TN);
    const int tm = t / (BN / TN);

    float acc[TM][TN];
#pragma unroll
    for (int i = 0; i < TM; i++)
#pragma unroll
        for (int j = 0; j < TN; j++) acc[i][j] = 0.f;

    const int wm = (t * 4) / BK;
    const int wk = (t * 4) % BK;
    const int xk = (t * 4) / BN;
    const int xn = (t * 4) % BN;

    for (int k0 = 0; k0 < K; k0 += BK) {
        float4 w4 = *(const float4*)(W + (long)(m0 + wm) * K + k0 + wk);
        Wsm[wk + 0][wm] = w4.x; Wsm[wk + 1][wm] = w4.y;
        Wsm[wk + 2][wm] = w4.z; Wsm[wk + 3][wm] = w4.w;
        float4 x4 = *(const float4*)(Xb + (long)(k0 + xk) * S + n0 + xn);
        *(float4*)&Xsm[xk][xn] = x4;
        __syncthreads();

#pragma unroll
        for (int kk = 0; kk < BK; kk++) {
            float a[TM], bb[TN];
#pragma unroll
            for (int i = 0; i < TM; i += 4) {
                float4 v = *(const float4*)&Wsm[kk][tm * TM + i];
                a[i] = v.x; a[i+1] = v.y; a[i+2] = v.z; a[i+3] = v.w;
            }
#pragma unroll
            for (int j = 0; j < TN; j += 4) {
                float4 v = *(const float4*)&Xsm[kk][tn * TN + j];
                bb[j] = v.x; bb[j+1] = v.y; bb[j+2] = v.z; bb[j+3] = v.w;
            }
#pragma unroll
            for (int i = 0; i < TM; i++)
#pragma unroll
                for (int j = 0; j < TN; j++) acc[i][j] += a[i] * bb[j];
        }
        __syncthreads();
    }

#pragma unroll
    for (int i = 0; i < TM; i++) {
        const int m = m0 + tm * TM + i;
        const float bv = (bias != nullptr) ? bias[m] : 0.f;
        float* yrow = Yb + (long)m * S + n0 + tn * TN;
#pragma unroll
        for (int j = 0; j < TN; j += 4) {
            float4 v;
            float e0 = acc[i][j+0] + bv, e1 = acc[i][j+1] + bv;
            float e2 = acc[i][j+2] + bv, e3 = acc[i][j+3] + bv;
            if (ACT == 1) { e0=fmaxf(e0,0.f); e1=fmaxf(e1,0.f);
                            e2=fmaxf(e2,0.f); e3=fmaxf(e3,0.f); }
            if (ACT == 2) { e0=fabsf(e0); e1=fabsf(e1); e2=fabsf(e2); e3=fabsf(e3); }
            v.x=e0; v.y=e1; v.z=e2; v.w=e3;
            *(float4*)(yrow + j) = v;
        }
    }
}

// ------ P[b,o,k] = (1/S) sum_s occ[b,o,s] * y1[b,k,s]  (split-K atomics) ------
__global__ __launch_bounds__(256)
void pool_contract(const float* __restrict__ Occ, const float* __restrict__ Y1,
                   float* __restrict__ P)
{
    const int S = SS;
    const int bz = blockIdx.z;
    const int b  = bz / NSPLIT;
    const int sp = bz % NSPLIT;
    const int chunk = S / NSPLIT;
    const int sbeg  = sp * chunk;

    const float* Ab = Occ + (long)b * COUT * S;
    const float* Fb = Y1  + (long)b * CIN  * S;
    const int n0 = blockIdx.x * 64;

    __shared__ float As[16][64 + 4];
    __shared__ float Bs[16][64 + 4];

    const int t  = threadIdx.x;
    const int tn = t % 16;
    const int tm = t / 16;
    const int lrow = t >> 2;
    const int lk   = (t & 3) * 4;

    float acc[4][4];
#pragma unroll
    for (int i = 0; i < 4; i++)
#pragma unroll
        for (int j = 0; j < 4; j++) acc[i][j] = 0.f;

    for (int s0 = sbeg; s0 < sbeg + chunk; s0 += 16) {
        float4 a4 = *(const float4*)(Ab + (long)lrow * S + s0 + lk);
        As[lk+0][lrow] = a4.x; As[lk+1][lrow] = a4.y;
        As[lk+2][lrow] = a4.z; As[lk+3][lrow] = a4.w;
        float4 f4 = *(const float4*)(Fb + (long)(n0 + lrow) * S + s0 + lk);
        Bs[lk+0][lrow] = f4.x; Bs[lk+1][lrow] = f4.y;
        Bs[lk+2][lrow] = f4.z; Bs[lk+3][lrow] = f4.w;
        __syncthreads();

#pragma unroll
        for (int kk = 0; kk < 16; kk++) {
            float4 av = *(const float4*)&As[kk][tm * 4];
            float4 bv = *(const float4*)&Bs[kk][tn * 4];
            float a[4] = {av.x, av.y, av.z, av.w};
            float c[4] = {bv.x, bv.y, bv.z, bv.w};
#pragma unroll
            for (int i = 0; i < 4; i++)
#pragma unroll
                for (int j = 0; j < 4; j++) acc[i][j] += a[i] * c[j];
        }
        __syncthreads();
    }

    const float scale = 1.0f / (float)S;
#pragma unroll
    for (int i = 0; i < 4; i++)
#pragma unroll
        for (int j = 0; j < 4; j++) {
            const int o = tm * 4 + i;
            const int k = n0 + tn * 4 + j;
            atomicAdd(&P[((long)b * COUT + o) * CIN + k], acc[i][j] * scale);
        }
}

// ------ q[b,o] = (1/S) sum_s occ[b,o,s] --------------------------------------
__global__ __launch_bounds__(256)
void qsum(const float* __restrict__ Occ, float* __restrict__ q)
{
    const int row = blockIdx.x;
    const float* src = Occ + (long)row * SS;
    const int t = threadIdx.x;
    float s = 0.f;
    for (int i = t * 4; i < SS; i += 1024) {
        float4 v = *(const float4*)(src + i);
        s += v.x + v.y + v.z + v.w;
    }
#pragma unroll
    for (int o = 16; o > 0; o >>= 1) s += __shfl_xor_sync(0xffffffff, s, o);
    __shared__ float red[8];
    if ((t & 31) == 0) red[t >> 5] = s;
    __syncthreads();
    if (t == 0) {
        float tot = 0.f;
#pragma unroll
        for (int i = 0; i < 8; ++i) tot += red[i];
        q[row] = tot / (float)SS;
    }
}

// ------ out[b,o,c] = sum_k P[b,o,k]*W2[c,k] + q[b,o]*b2[c] -------------------
__global__ __launch_bounds__(256)
void fin_gemm(const float* __restrict__ P, const float* __restrict__ q,
              const float* __restrict__ W2, const float* __restrict__ b2,
              float* __restrict__ out)
{
    const int b = blockIdx.z, c0 = blockIdx.x * 64;
    __shared__ float Pt[64][68];
    __shared__ float Wt[64][68];
    const int t = threadIdx.x;
    const int tm = t >> 4, tn = t & 15;

    float acc[4][4];
#pragma unroll
    for (int i = 0; i < 4; i++)
#pragma unroll
        for (int j = 0; j < 4; j++) acc[i][j] = 0.f;

    for (int k0 = 0; k0 < CIN; k0 += 64) {
#pragma unroll
        for (int i = 0; i < 4; ++i) {
            const int r  = (t >> 4) + i * 16;
            const int kc = (t & 15) * 4;
            *(float4*)&Pt[r][kc] = *(const float4*)(P + ((long)b * COUT + r) * CIN + k0 + kc);
            *(float4*)&Wt[r][kc] = *(const float4*)(W2 + (long)(c0 + r) * CIN + k0 + kc);
        }
        __syncthreads();
#pragma unroll
        for (int kk = 0; kk < 64; ++kk) {
            float a[4], w[4];
#pragma unroll
            for (int i = 0; i < 4; ++i) a[i] = Pt[tm * 4 + i][kk];
#pragma unroll
            for (int j = 0; j < 4; ++j) w[j] = Wt[tn * 4 + j][kk];
#pragma unroll
            for (int i = 0; i < 4; ++i)
#pragma unroll
                for (int j = 0; j < 4; ++j) acc[i][j] += a[i] * w[j];
        }
        __syncthreads();
    }

#pragma unroll
    for (int i = 0; i < 4; ++i) {
        const int o = tm * 4 + i;
        const float qv = q[b * COUT + o];
#pragma unroll
        for (int j = 0; j < 4; ++j) {
            const int c = c0 + tn * 4 + j;
            out[((long)b * COUT + o) * CIN + c] = acc[i][j] + qv * b2[c];
        }
    }
}

__global__ void zero_buf(float* o, int n)
{
    int i = blockIdx.x * blockDim.x + threadIdx.x;
    if (i < n) o[i] = 0.f;
}

// -----------------------------------------------------------------------------
extern "C" void kernel_launch(void* const* d_in, const int* in_sizes, int n_in,
                              void* d_out, int out_size)
{
    const float* x      = (const float*)d_in[0];
    const float* w_add1 = (const float*)d_in[1];
    const float* b_add1 = (const float*)d_in[2];
    const float* w_add2 = (const float*)d_in[3];
    const float* b_add2 = (const float*)d_in[4];
    const float* w_occ1 = (const float*)d_in[5];
    const float* b_occ1 = (const float*)d_in[6];
    const float* w_occ2 = (const float*)d_in[7];
    const float* b_occ2 = (const float*)d_in[8];
    const float* w_occ3 = (const float*)d_in[9];
    float* out = (float*)d_out;

    __nv_bfloat16 *wch, *wcl;
    float *y1, *h1, *h2, *occ, *P, *q, *bc;
    cudaGetSymbolAddress((void**)&y1,  g_y1);
    cudaGetSymbolAddress((void**)&h1,  g_h1);
    cudaGetSymbolAddress((void**)&h2,  g_h2);
    cudaGetSymbolAddress((void**)&occ, g_occ);
    cudaGetSymbolAddress((void**)&P,   g_P);
    cudaGetSymbolAddress((void**)&q,   g_q);
    cudaGetSymbolAddress((void**)&wch, g_wch);
    cudaGetSymbolAddress((void**)&wcl, g_wcl);
    cudaGetSymbolAddress((void**)&bc,  g_bc);

    cudaFuncSetAttribute(fused_gemm, cudaFuncAttributeMaxDynamicSharedMemorySize, HSMEM);

    // pre-passes: split/concat weights + bias; zero P accumulator
    wsplit<<<(CIN*CIN + 255) / 256, 256>>>(w_add1, wch, wcl, CIN*CIN);
    wsplit<<<(128*CIN + 255) / 256, 256>>>(w_occ1, wch + 512*CIN, wcl + 512*CIN, 128*CIN);
    bconcat<<<(MTOT + 255) / 256, 256>>>(b_add1, b_occ1, bc);
    zero_buf<<<(NB*COUT*CIN + 255) / 256, 256>>>(P, NB*COUT*CIN);

    // fused add1 + occ1: rows 0..511 -> y1, rows 512..639 -> h1
    fused_gemm<<<dim3(SS/128, MTOT/128, NB), 256, HSMEM>>>(wch, wcl, x, bc, y1, h1);

    // occ tail (SIMT)
    gemm_bias_act<64,64,16,4,4,1><<<dim3(SS/64, 1, NB), 256>>>(h1, w_occ2, b_occ2, h2, 64, 128);
    gemm_bias_act<64,64,16,4,4,2><<<dim3(SS/64, 1, NB), 256>>>(h2, w_occ3, nullptr, occ, 64, 64);

    // P = (1/S) occ . y1^T ;  q = (1/S) row-sums of occ
    pool_contract<<<dim3(CIN/64, 1, NB * NSPLIT), 256>>>(occ, y1, P);
    qsum<<<NB * COUT, 256>>>(occ, q);

    // out = P . W2^T + q b2^T
    fin_gemm<<<dim3(CIN/64, 1, NB), 256>>>(P, q, w_add2, b_add2, out);
}

// round 8
// speedup vs baseline: 1.0223x; 1.0223x over previous
#include <cuda_runtime.h>
#include <cuda_bf16.h>
#include <mma.h>
#include <cstdint>

using namespace nvcuda;

#define NB   4
#define CIN  512
#define COUT 64
#define SS   16384   // T*H*W
#define NSPLIT 32
#define MTOT 640     // 512 (add1) + 128 (occ1) fused rows

// ---------------- scratch (device globals; no allocs allowed) ----------------
__device__ __nv_bfloat16 g_xt_hi[(size_t)NB * SS * CIN];
__device__ __nv_bfloat16 g_xt_lo[(size_t)NB * SS * CIN];
__device__ float g_y1  [(size_t)NB * CIN * SS];   // relu(add1) fp32 (B,512,S)
__device__ float g_h1  [(size_t)NB * 128 * SS];   // relu(occ1)
__device__ float g_occ [(size_t)NB *  64 * SS];
__device__ float g_P   [(size_t)NB * COUT * CIN];
__device__ float g_q   [(size_t)NB * COUT];
__device__ __nv_bfloat16 g_wch[MTOT * CIN];       // concat W rows, hi
__device__ __nv_bfloat16 g_wcl[MTOT * CIN];       // concat W rows, lo
__device__ float g_bc[MTOT];                      // concat bias

// ---------------- helpers ----------------------------------------------------
__device__ __forceinline__ uint32_t smem_u32(const void* p) {
    uint32_t a;
    asm("{ .reg .u64 t; cvta.to.shared.u64 t, %1; cvt.u32.u64 %0, t; }" : "=r"(a) : "l"(p));
    return a;
}
__device__ __forceinline__ void cp16(uint32_t dst, const void* src) {
    asm volatile("cp.async.cg.shared.global [%0], [%1], 16;" :: "r"(dst), "l"(src));
}
__device__ __forceinline__ void cp_commit() {
    asm volatile("cp.async.commit_group;" ::: "memory");
}
template<int N>
__device__ __forceinline__ void cp_wait() {
    asm volatile("cp.async.wait_group %0;" :: "n"(N) : "memory");
}

// ---------------- merged HMMA GEMM (R5 body + routed epilogue) ---------------
// D(128x128) = Wc(640,512) x Xt^T ; A bf16 hi/lo rows, B = xt rows bf16 hi/lo.
// 3-term: Ahi*Bhi + Ahi*Blo + Alo*Bhi (fp32 accum). bias+relu.
// rows m0<512 -> y1 (B,512,S); rows m0>=512 -> h1 (B,128,S).
#define STAGE_B  40960          // 4 tiles x 128 rows x 80B
#define TILE_B   10240
#define HSMEM    81920
__global__ __launch_bounds__(256)
void hmma_gemm(const __nv_bfloat16* __restrict__ Wh, const __nv_bfloat16* __restrict__ Wl,
               const __nv_bfloat16* __restrict__ Bh,  const __nv_bfloat16* __restrict__ Bl,
               const float* __restrict__ bias,
               float* __restrict__ Y1, float* __restrict__ H1)
{
    extern __shared__ __align__(128) char smem[];
    const int t = threadIdx.x, wid = t >> 5;
    const int n0 = blockIdx.x * 128, m0 = blockIdx.y * 128, b = blockIdx.z;
    const long brow = (long)b * SS + n0;
    const uint32_t sb = smem_u32(smem);

    const int wm = wid & 3;        // 4 warp rows -> 32 m each
    const int wn = wid >> 2;       // 2 warp cols -> 64 n each

    const __nv_bfloat16* bases[4] = {
        Wh + (long)m0 * 512, Wl + (long)m0 * 512,
        Bh + brow * 512, Bl + brow * 512 };

    auto load_chunk = [&](int c, int st) {
        const int k0 = c * 32;
#pragma unroll
        for (int i = 0; i < 8; ++i) {
            const int vid = t + i * 256;
            const int tile = vid >> 9;
            const int r    = (vid >> 2) & 127;
            const int v    = vid & 3;
            cp16(sb + st * STAGE_B + tile * TILE_B + r * 80 + v * 16,
                 bases[tile] + (long)r * 512 + k0 + v * 8);
        }
        cp_commit();
    };

    wmma::fragment<wmma::accumulator, 16, 16, 16, float> acc[2][4];
#pragma unroll
    for (int i = 0; i < 2; ++i)
#pragma unroll
        for (int j = 0; j < 4; ++j) wmma::fill_fragment(acc[i][j], 0.0f);

    load_chunk(0, 0);

    for (int c = 0; c < 16; ++c) {
        const int st = c & 1;
        if (c + 1 < 16) { load_chunk(c + 1, st ^ 1); cp_wait<1>(); }
        else            { cp_wait<0>(); }
        __syncthreads();

        const __nv_bfloat16* Ah  = (const __nv_bfloat16*)(smem + st * STAGE_B);
        const __nv_bfloat16* Al  = Ah + 5120;
        const __nv_bfloat16* Bhs = Ah + 10240;
        const __nv_bfloat16* Bls = Ah + 15360;

#pragma unroll
        for (int kk = 0; kk < 32; kk += 16) {
            wmma::fragment<wmma::matrix_a, 16, 16, 16, __nv_bfloat16, wmma::row_major> fah[2], fal[2];
            wmma::fragment<wmma::matrix_b, 16, 16, 16, __nv_bfloat16, wmma::col_major> fbh[4], fbl[4];
#pragma unroll
            for (int i = 0; i < 2; ++i) {
                wmma::load_matrix_sync(fah[i], Ah + (wm * 32 + i * 16) * 40 + kk, 40);
                wmma::load_matrix_sync(fal[i], Al + (wm * 32 + i * 16) * 40 + kk, 40);
            }
#pragma unroll
            for (int j = 0; j < 4; ++j) {
                wmma::load_matrix_sync(fbh[j], Bhs + (wn * 64 + j * 16) * 40 + kk, 40);
                wmma::load_matrix_sync(fbl[j], Bls + (wn * 64 + j * 16) * 40 + kk, 40);
            }
#pragma unroll
            for (int i = 0; i < 2; ++i)
#pragma unroll
                for (int j = 0; j < 4; ++j) {
                    wmma::mma_sync(acc[i][j], fah[i], fbh[j], acc[i][j]);
                    wmma::mma_sync(acc[i][j], fah[i], fbl[j], acc[i][j]);
                    wmma::mma_sync(acc[i][j], fal[i], fbh[j], acc[i][j]);
                }
        }
        __syncthreads();
    }

    // ---- epilogue: bias + relu, routed ----
    float* Dsm = (float*)smem;    // [m][n] 128 x 132
#pragma unroll
    for (int i = 0; i < 2; ++i)
#pragma unroll
        for (int j = 0; j < 4; ++j)
            wmma::store_matrix_sync(Dsm + (wm * 32 + i * 16) * 132 + wn * 64 + j * 16,
                                    acc[i][j], 132, wmma::mem_row_major);
    __syncthreads();
    const int r  = t >> 1;
    const int cb = (t & 1) * 64;
    const float bv = bias[m0 + r];
    float* yr = (m0 < 512)
              ? Y1 + ((long)b * CIN + m0 + r) * SS + n0 + cb
              : H1 + ((long)b * 128 + (m0 - 512) + r) * SS + n0 + cb;
#pragma unroll
    for (int j = 0; j < 64; j += 4) {
        float4 v;
        v.x = fmaxf(Dsm[r * 132 + cb + j + 0] + bv, 0.f);
        v.y = fmaxf(Dsm[r * 132 + cb + j + 1] + bv, 0.f);
        v.z = fmaxf(Dsm[r * 132 + cb + j + 2] + bv, 0.f);
        v.w = fmaxf(Dsm[r * 132 + cb + j + 3] + bv, 0.f);
        *(float4*)(yr + j) = v;
    }
}

// ---------------- pre-passes --------------------------------------------------
__global__ __launch_bounds__(256)
void transpose_split(const float* __restrict__ X,
                     __nv_bfloat16* __restrict__ H, __nv_bfloat16* __restrict__ L)
{
    __shared__ float tile[32][33];
    const int s0 = blockIdx.x * 32, c0 = blockIdx.y * 32, b = blockIdx.z;
    const int tx = threadIdx.x, ty = threadIdx.y;   // 32 x 8
    const float* Xb = X + ((long)b * CIN + c0) * SS + s0;
#pragma unroll
    for (int j = 0; j < 4; ++j)
        tile[ty + 8 * j][tx] = Xb[(long)(ty + 8 * j) * SS + tx];
    __syncthreads();
#pragma unroll
    for (int j = 0; j < 4; ++j) {
        const int s = ty + 8 * j;
        float v = tile[tx][s];
        const long off = ((long)b * SS + s0 + s) * CIN + c0 + tx;
        __nv_bfloat16 hi = __float2bfloat16(v);
        H[off] = hi;
        L[off] = __float2bfloat16(v - __bfloat162float(hi));
    }
}

__global__ void wsplit(const float* __restrict__ W,
                       __nv_bfloat16* __restrict__ H, __nv_bfloat16* __restrict__ L, int n)
{
    int i = blockIdx.x * 256 + threadIdx.x;
    if (i < n) {
        float v = W[i];
        __nv_bfloat16 h = __float2bfloat16(v);
        H[i] = h;
        L[i] = __float2bfloat16(v - __bfloat162float(h));
    }
}

__global__ void bconcat(const float* __restrict__ b1, const float* __restrict__ bo1,
                        float* __restrict__ bc)
{
    int i = blockIdx.x * 256 + threadIdx.x;
    if (i < 512) bc[i] = b1[i];
    else if (i < MTOT) bc[i] = bo1[i - 512];
}

// -------- fused occ tail: h2 = relu(Wo2 h1 + b), occ = |Wo3 h2|, q += sums ----
// grid (SS/128, 1, NB), 256 threads, dynamic smem.
#define W2OFF 0
#define W3OFF 33792
#define H1OFF 51200
#define H2OFF 68096
#define OSMEM 101888
__global__ __launch_bounds__(256)
void occ_tail(const float* __restrict__ h1, const float* __restrict__ wo2,
              const float* __restrict__ bo2, const float* __restrict__ wo3,
              float* __restrict__ occ, float* __restrict__ q)
{
    extern __shared__ __align__(16) char smem[];
    float* W2s = (float*)(smem + W2OFF);   // [64][132]
    float* W3s = (float*)(smem + W3OFF);   // [64][68]
    float* H1s = (float*)(smem + H1OFF);   // [32][132]
    float* H2s = (float*)(smem + H2OFF);   // [64][132]

    const int t = threadIdx.x;
    const int s0 = blockIdx.x * 128, b = blockIdx.z;
    const int tm = t >> 4, tn = t & 15;    // 16 x 16

    // load weights
#pragma unroll
    for (int i = 0; i < 8; ++i) {
        const int vid = t + i * 256;
        const int r = vid >> 5, c4 = (vid & 31) * 4;
        *(float4*)&W2s[r * 132 + c4] = *(const float4*)(wo2 + r * 128 + c4);
    }
#pragma unroll
    for (int i = 0; i < 4; ++i) {
        const int vid = t + i * 256;
        const int r = vid >> 4, c4 = (vid & 15) * 4;
        *(float4*)&W3s[r * 68 + c4] = *(const float4*)(wo3 + r * 64 + c4);
    }

    // stage 1: h2 = relu(Wo2 . h1 + b)
    float acc1[4][8];
#pragma unroll
    for (int i = 0; i < 4; ++i)
#pragma unroll
        for (int j = 0; j < 8; ++j) acc1[i][j] = 0.f;

    for (int c0 = 0; c0 < 128; c0 += 32) {
        __syncthreads();
#pragma unroll
        for (int i = 0; i < 4; ++i) {
            const int vid = t + i * 256;
            const int r = vid >> 5, sc = (vid & 31) * 4;
            *(float4*)&H1s[r * 132 + sc] =
                *(const float4*)(h1 + ((long)b * 128 + c0 + r) * SS + s0 + sc);
        }
        __syncthreads();
#pragma unroll
        for (int kk = 0; kk < 32; ++kk) {
            float a[4], v[8];
#pragma unroll
            for (int i = 0; i < 4; ++i) a[i] = W2s[(tm * 4 + i) * 132 + c0 + kk];
#pragma unroll
            for (int j = 0; j < 8; ++j) v[j] = H1s[kk * 132 + tn * 8 + j];
#pragma unroll
            for (int i = 0; i < 4; ++i)
#pragma unroll
                for (int j = 0; j < 8; ++j) acc1[i][j] += a[i] * v[j];
        }
    }
    __syncthreads();
#pragma unroll
    for (int i = 0; i < 4; ++i) {
        const float bv = bo2[tm * 4 + i];
#pragma unroll
        for (int j = 0; j < 8; ++j)
            H2s[(tm * 4 + i) * 132 + tn * 8 + j] = fmaxf(acc1[i][j] + bv, 0.f);
    }
    __syncthreads();

    // stage 2: occ = |Wo3 . h2| ; q partials
    float acc2[4][8];
#pragma unroll
    for (int i = 0; i < 4; ++i)
#pragma unroll
        for (int j = 0; j < 8; ++j) acc2[i][j] = 0.f;
#pragma unroll
    for (int kk = 0; kk < 64; ++kk) {
        float a[4], v[8];
#pragma unroll
        for (int i = 0; i < 4; ++i) a[i] = W3s[(tm * 4 + i) * 68 + kk];
#pragma unroll
        for (int j = 0; j < 8; ++j) v[j] = H2s[kk * 132 + tn * 8 + j];
#pragma unroll
        for (int i = 0; i < 4; ++i)
#pragma unroll
            for (int j = 0; j < 8; ++j) acc2[i][j] += a[i] * v[j];
    }
#pragma unroll
    for (int i = 0; i < 4; ++i) {
        const int o = tm * 4 + i;
        float qp = 0.f;
        float4 v0, v1;
        float* dst = occ + ((long)b * COUT + o) * SS + s0 + tn * 8;
        v0.x = fabsf(acc2[i][0]); v0.y = fabsf(acc2[i][1]);
        v0.z = fabsf(acc2[i][2]); v0.w = fabsf(acc2[i][3]);
        v1.x = fabsf(acc2[i][4]); v1.y = fabsf(acc2[i][5]);
        v1.z = fabsf(acc2[i][6]); v1.w = fabsf(acc2[i][7]);
        *(float4*)dst = v0;
        *(float4*)(dst + 4) = v1;
        qp = v0.x + v0.y + v0.z + v0.w + v1.x + v1.y + v1.z + v1.w;
        // reduce across the 16 tn lanes (stay within 16-lane group)
#pragma unroll
        for (int off = 8; off > 0; off >>= 1)
            qp += __shfl_xor_sync(0xffffffff, qp, off);
        if (tn == 0) atomicAdd(&q[b * COUT + o], qp * (1.0f / (float)SS));
    }
}

// ------ P[b,o,k] = (1/S) sum_s occ[b,o,s] * y1[b,k,s]  (split-K atomics) ------
__global__ __launch_bounds__(256)
void pool_contract(const float* __restrict__ Occ, const float* __restrict__ Y1,
                   float* __restrict__ P)
{
    const int bz = blockIdx.z;
    const int b  = bz / NSPLIT;
    const int sp = bz % NSPLIT;
    const int chunk = SS / NSPLIT;          // 512
    const int sbeg  = sp * chunk;

    const float* Ab = Occ + (long)b * COUT * SS;
    const float* Fb = Y1  + (long)b * CIN  * SS;
    const int n0 = blockIdx.x * 128;

    __shared__ float As[16][68];
    __shared__ float Bs[16][132];

    const int t  = threadIdx.x;
    const int tm = t >> 4, tn = t & 15;     // 16 x 16 -> 4o x 8k per thread
    const int lrA = t >> 2, lkA = (t & 3) * 4;
    const int lrB = t >> 1, lkB = (t & 1) * 8;

    float acc[4][8];
#pragma unroll
    for (int i = 0; i < 4; i++)
#pragma unroll
        for (int j = 0; j < 8; j++) acc[i][j] = 0.f;

    for (int s0 = sbeg; s0 < sbeg + chunk; s0 += 16) {
        float4 a4 = *(const float4*)(Ab + (long)lrA * SS + s0 + lkA);
        As[lkA+0][lrA] = a4.x; As[lkA+1][lrA] = a4.y;
        As[lkA+2][lrA] = a4.z; As[lkA+3][lrA] = a4.w;
        float4 f0 = *(const float4*)(Fb + (long)(n0 + lrB) * SS + s0 + lkB);
        float4 f1 = *(const float4*)(Fb + (long)(n0 + lrB) * SS + s0 + lkB + 4);
        Bs[lkB+0][lrB] = f0.x; Bs[lkB+1][lrB] = f0.y;
        Bs[lkB+2][lrB] = f0.z; Bs[lkB+3][lrB] = f0.w;
        Bs[lkB+4][lrB] = f1.x; Bs[lkB+5][lrB] = f1.y;
        Bs[lkB+6][lrB] = f1.z; Bs[lkB+7][lrB] = f1.w;
        __syncthreads();

#pragma unroll
        for (int kk = 0; kk < 16; kk++) {
            float a[4], c[8];
#pragma unroll
            for (int i = 0; i < 4; ++i) a[i] = As[kk][tm * 4 + i];
#pragma unroll
            for (int j = 0; j < 8; ++j) c[j] = Bs[kk][tn * 8 + j];
#pragma unroll
            for (int i = 0; i < 4; i++)
#pragma unroll
                for (int j = 0; j < 8; j++) acc[i][j] += a[i] * c[j];
        }
        __syncthreads();
    }

    const float scale = 1.0f / (float)SS;
#pragma unroll
    for (int i = 0; i < 4; i++)
#pragma unroll
        for (int j = 0; j < 8; j++) {
            const int o = tm * 4 + i;
            const int k = n0 + tn * 8 + j;
            atomicAdd(&P[((long)b * COUT + o) * CIN + k], acc[i][j] * scale);
        }
}

// ------ out[b,o,c] = sum_k P[b,o,k]*W2[c,k] + q[b,o]*b2[c] -------------------
__global__ __launch_bounds__(256)
void fin_gemm(const float* __restrict__ P, const float* __restrict__ q,
              const float* __restrict__ W2, const float* __restrict__ b2,
              float* __restrict__ out)
{
    const int b = blockIdx.z, c0 = blockIdx.x * 64;
    __shared__ float Pt[64][68];
    __shared__ float Wt[64][68];
    const int t = threadIdx.x;
    const int tm = t >> 4, tn = t & 15;

    float acc[4][4];
#pragma unroll
    for (int i = 0; i < 4; i++)
#pragma unroll
        for (int j = 0; j < 4; j++) acc[i][j] = 0.f;

    for (int k0 = 0; k0 < CIN; k0 += 64) {
#pragma unroll
        for (int i = 0; i < 4; ++i) {
            const int r  = (t >> 4) + i * 16;
            const int kc = (t & 15) * 4;
            *(float4*)&Pt[r][kc] = *(const float4*)(P + ((long)b * COUT + r) * CIN + k0 + kc);
            *(float4*)&Wt[r][kc] = *(const float4*)(W2 + (long)(c0 + r) * CIN + k0 + kc);
        }
        __syncthreads();
#pragma unroll
        for (int kk = 0; kk < 64; ++kk) {
            float a[4], w[4];
#pragma unroll
            for (int i = 0; i < 4; ++i) a[i] = Pt[tm * 4 + i][kk];
#pragma unroll
            for (int j = 0; j < 4; ++j) w[j] = Wt[tn * 4 + j][kk];
#pragma unroll
            for (int i = 0; i < 4; ++i)
#pragma unroll
                for (int j = 0; j < 4; ++j) acc[i][j] += a[i] * w[j];
        }
        __syncthreads();
    }

#pragma unroll
    for (int i = 0; i < 4; ++i) {
        const int o = tm * 4 + i;
        const float qv = q[b * COUT + o];
#pragma unroll
        for (int j = 0; j < 4; ++j) {
            const int c = c0 + tn * 4 + j;
            out[((long)b * COUT + o) * CIN + c] = acc[i][j] + qv * b2[c];
        }
    }
}

__global__ void zero_buf(float* o, int n)
{
    int i = blockIdx.x * blockDim.x + threadIdx.x;
    if (i < n) o[i] = 0.f;
}

// -----------------------------------------------------------------------------
extern "C" void kernel_launch(void* const* d_in, const int* in_sizes, int n_in,
                              void* d_out, int out_size)
{
    const float* x      = (const float*)d_in[0];
    const float* w_add1 = (const float*)d_in[1];
    const float* b_add1 = (const float*)d_in[2];
    const float* w_add2 = (const float*)d_in[3];
    const float* b_add2 = (const float*)d_in[4];
    const float* w_occ1 = (const float*)d_in[5];
    const float* b_occ1 = (const float*)d_in[6];
    const float* w_occ2 = (const float*)d_in[7];
    const float* b_occ2 = (const float*)d_in[8];
    const float* w_occ3 = (const float*)d_in[9];
    float* out = (float*)d_out;

    __nv_bfloat16 *xth, *xtl, *wch, *wcl;
    float *y1, *h1, *occ, *P, *q, *bc;
    cudaGetSymbolAddress((void**)&xth, g_xt_hi);
    cudaGetSymbolAddress((void**)&xtl, g_xt_lo);
    cudaGetSymbolAddress((void**)&y1,  g_y1);
    cudaGetSymbolAddress((void**)&h1,  g_h1);
    cudaGetSymbolAddress((void**)&occ, g_occ);
    cudaGetSymbolAddress((void**)&P,   g_P);
    cudaGetSymbolAddress((void**)&q,   g_q);
    cudaGetSymbolAddress((void**)&wch, g_wch);
    cudaGetSymbolAddress((void**)&wcl, g_wcl);
    cudaGetSymbolAddress((void**)&bc,  g_bc);

    cudaFuncSetAttribute(hmma_gemm, cudaFuncAttributeMaxDynamicSharedMemorySize, HSMEM);
    cudaFuncSetAttribute(occ_tail,  cudaFuncAttributeMaxDynamicSharedMemorySize, OSMEM);

    // pre-passes
    wsplit<<<(CIN*CIN + 255) / 256, 256>>>(w_add1, wch, wcl, CIN*CIN);
    wsplit<<<(128*CIN + 255) / 256, 256>>>(w_occ1, wch + 512*CIN, wcl + 512*CIN, 128*CIN);
    bconcat<<<(MTOT + 255) / 256, 256>>>(b_add1, b_occ1, bc);
    zero_buf<<<(NB*COUT*CIN + 255) / 256, 256>>>(P, NB*COUT*CIN);
    zero_buf<<<1, 256>>>(q, NB*COUT);
    transpose_split<<<dim3(SS/32, CIN/32, NB), dim3(32, 8)>>>(x, xth, xtl);

    // merged add1 + occ1: rows 0..511 -> y1, rows 512..639 -> h1
    hmma_gemm<<<dim3(SS/128, MTOT/128, NB), 256, HSMEM>>>(wch, wcl, xth, xtl, bc, y1, h1);

    // fused occ tail (occ2 + occ3 + q)
    occ_tail<<<dim3(SS/128, 1, NB), 256, OSMEM>>>(h1, w_occ2, b_occ2, w_occ3, occ, q);

    // P = (1/S) occ . y1^T
    pool_contract<<<dim3(CIN/128, 1, NB * NSPLIT), 256>>>(occ, y1, P);

    // out = P . W2^T + q b2^T
    fin_gemm<<<dim3(CIN/64, 1, NB), 256>>>(P, q, w_add2, b_add2, out);
}

// round 9
// speedup vs baseline: 1.1413x; 1.1164x over previous
#include <cuda_runtime.h>
#include <cuda_bf16.h>
#include <mma.h>
#include <cstdint>

using namespace nvcuda;

#define NB   4
#define CIN  512
#define COUT 64
#define SS   16384   // T*H*W
#define NSPLIT 32
#define MTOT 640     // 512 (add1) + 128 (occ1) fused rows

// ---------------- scratch (device globals; no allocs allowed) ----------------
__device__ __nv_bfloat16 g_xt_hi[(size_t)NB * SS * CIN];
__device__ __nv_bfloat16 g_xt_lo[(size_t)NB * SS * CIN];
__device__ float g_y1  [(size_t)NB * CIN * SS];   // relu(add1) fp32 (B,512,S)
__device__ float g_h1  [(size_t)NB * 128 * SS];   // relu(occ1)
__device__ float g_occ [(size_t)NB *  64 * SS];
__device__ float g_P   [(size_t)NB * COUT * CIN];
__device__ float g_q   [(size_t)NB * COUT];
__device__ __nv_bfloat16 g_wch[MTOT * CIN];       // concat W rows, hi
__device__ __nv_bfloat16 g_wcl[MTOT * CIN];       // concat W rows, lo
__device__ float g_bc[MTOT];                      // concat bias

// ---------------- helpers ----------------------------------------------------
__device__ __forceinline__ uint32_t smem_u32(const void* p) {
    uint32_t a;
    asm("{ .reg .u64 t; cvta.to.shared.u64 t, %1; cvt.u32.u64 %0, t; }" : "=r"(a) : "l"(p));
    return a;
}
__device__ __forceinline__ void cp16(uint32_t dst, const void* src) {
    asm volatile("cp.async.cg.shared.global [%0], [%1], 16;" :: "r"(dst), "l"(src));
}
__device__ __forceinline__ void cp_commit() {
    asm volatile("cp.async.commit_group;" ::: "memory");
}
template<int N>
__device__ __forceinline__ void cp_wait() {
    asm volatile("cp.async.wait_group %0;" :: "n"(N) : "memory");
}

// ---------------- pre-passes (3 launches so hmma_gemm is launch #4) ----------
__global__ __launch_bounds__(256)
void transpose_split(const float* __restrict__ X,
                     __nv_bfloat16* __restrict__ H, __nv_bfloat16* __restrict__ L)
{
    __shared__ float tile[32][33];
    const int s0 = blockIdx.x * 32, c0 = blockIdx.y * 32, b = blockIdx.z;
    const int tx = threadIdx.x, ty = threadIdx.y;   // 32 x 8
    const float* Xb = X + ((long)b * CIN + c0) * SS + s0;
#pragma unroll
    for (int j = 0; j < 4; ++j)
        tile[ty + 8 * j][tx] = Xb[(long)(ty + 8 * j) * SS + tx];
    __syncthreads();
#pragma unroll
    for (int j = 0; j < 4; ++j) {
        const int s = ty + 8 * j;
        float v = tile[tx][s];
        const long off = ((long)b * SS + s0 + s) * CIN + c0 + tx;
        __nv_bfloat16 hi = __float2bfloat16(v);
        H[off] = hi;
        L[off] = __float2bfloat16(v - __bfloat162float(hi));
    }
}

// split BOTH weight matrices into the concat hi/lo buffers in one launch
__global__ void wsplit_all(const float* __restrict__ W1, const float* __restrict__ Wo1,
                           __nv_bfloat16* __restrict__ H, __nv_bfloat16* __restrict__ L)
{
    int i = blockIdx.x * 256 + threadIdx.x;
    if (i >= MTOT * CIN) return;
    float v = (i < 512 * CIN) ? W1[i] : Wo1[i - 512 * CIN];
    __nv_bfloat16 h = __float2bfloat16(v);
    H[i] = h;
    L[i] = __float2bfloat16(v - __bfloat162float(h));
}

// bias concat + zero P + zero q, one launch
__global__ void prep(const float* __restrict__ b1, const float* __restrict__ bo1,
                     float* __restrict__ bc, float* __restrict__ P, float* __restrict__ q)
{
    int i = blockIdx.x * 256 + threadIdx.x;
    if (i < NB * COUT * CIN) P[i] = 0.f;
    if (i < NB * COUT) q[i] = 0.f;
    if (i < 512) bc[i] = b1[i];
    else if (i < MTOT) bc[i] = bo1[i - 512];
}

// ---------------- merged HMMA GEMM (R5 body + routed epilogue) ---------------
#define STAGE_B  40960          // 4 tiles x 128 rows x 80B
#define TILE_B   10240
#define HSMEM    81920
__global__ __launch_bounds__(256)
void hmma_gemm(const __nv_bfloat16* __restrict__ Wh, const __nv_bfloat16* __restrict__ Wl,
               const __nv_bfloat16* __restrict__ Bh,  const __nv_bfloat16* __restrict__ Bl,
               const float* __restrict__ bias,
               float* __restrict__ Y1, float* __restrict__ H1)
{
    extern __shared__ __align__(128) char smem[];
    const int t = threadIdx.x, wid = t >> 5;
    const int n0 = blockIdx.x * 128, m0 = blockIdx.y * 128, b = blockIdx.z;
    const long brow = (long)b * SS + n0;
    const uint32_t sb = smem_u32(smem);

    const int wm = wid & 3;        // 4 warp rows -> 32 m each
    const int wn = wid >> 2;       // 2 warp cols -> 64 n each

    const __nv_bfloat16* bases[4] = {
        Wh + (long)m0 * 512, Wl + (long)m0 * 512,
        Bh + brow * 512, Bl + brow * 512 };

    auto load_chunk = [&](int c, int st) {
        const int k0 = c * 32;
#pragma unroll
        for (int i = 0; i < 8; ++i) {
            const int vid = t + i * 256;
            const int tile = vid >> 9;
            const int r    = (vid >> 2) & 127;
            const int v    = vid & 3;
            cp16(sb + st * STAGE_B + tile * TILE_B + r * 80 + v * 16,
                 bases[tile] + (long)r * 512 + k0 + v * 8);
        }
        cp_commit();
    };

    wmma::fragment<wmma::accumulator, 16, 16, 16, float> acc[2][4];
#pragma unroll
    for (int i = 0; i < 2; ++i)
#pragma unroll
        for (int j = 0; j < 4; ++j) wmma::fill_fragment(acc[i][j], 0.0f);

    load_chunk(0, 0);

    for (int c = 0; c < 16; ++c) {
        const int st = c & 1;
        if (c + 1 < 16) { load_chunk(c + 1, st ^ 1); cp_wait<1>(); }
        else            { cp_wait<0>(); }
        __syncthreads();

        const __nv_bfloat16* Ah  = (const __nv_bfloat16*)(smem + st * STAGE_B);
        const __nv_bfloat16* Al  = Ah + 5120;
        const __nv_bfloat16* Bhs = Ah + 10240;
        const __nv_bfloat16* Bls = Ah + 15360;

#pragma unroll
        for (int kk = 0; kk < 32; kk += 16) {
            wmma::fragment<wmma::matrix_a, 16, 16, 16, __nv_bfloat16, wmma::row_major> fah[2], fal[2];
            wmma::fragment<wmma::matrix_b, 16, 16, 16, __nv_bfloat16, wmma::col_major> fbh[4], fbl[4];
#pragma unroll
            for (int i = 0; i < 2; ++i) {
                wmma::load_matrix_sync(fah[i], Ah + (wm * 32 + i * 16) * 40 + kk, 40);
                wmma::load_matrix_sync(fal[i], Al + (wm * 32 + i * 16) * 40 + kk, 40);
            }
#pragma unroll
            for (int j = 0; j < 4; ++j) {
                wmma::load_matrix_sync(fbh[j], Bhs + (wn * 64 + j * 16) * 40 + kk, 40);
                wmma::load_matrix_sync(fbl[j], Bls + (wn * 64 + j * 16) * 40 + kk, 40);
            }
#pragma unroll
            for (int i = 0; i < 2; ++i)
#pragma unroll
                for (int j = 0; j < 4; ++j) {
                    wmma::mma_sync(acc[i][j], fah[i], fbh[j], acc[i][j]);
                    wmma::mma_sync(acc[i][j], fah[i], fbl[j], acc[i][j]);
                    wmma::mma_sync(acc[i][j], fal[i], fbh[j], acc[i][j]);
                }
        }
        __syncthreads();
    }

    // ---- epilogue: bias + relu, routed ----
    float* Dsm = (float*)smem;    // [m][n] 128 x 132
#pragma unroll
    for (int i = 0; i < 2; ++i)
#pragma unroll
        for (int j = 0; j < 4; ++j)
            wmma::store_matrix_sync(Dsm + (wm * 32 + i * 16) * 132 + wn * 64 + j * 16,
                                    acc[i][j], 132, wmma::mem_row_major);
    __syncthreads();
    const int r  = t >> 1;
    const int cb = (t & 1) * 64;
    const float bv = bias[m0 + r];
    float* yr = (m0 < 512)
              ? Y1 + ((long)b * CIN + m0 + r) * SS + n0 + cb
              : H1 + ((long)b * 128 + (m0 - 512) + r) * SS + n0 + cb;
#pragma unroll
    for (int j = 0; j < 64; j += 4) {
        float4 v;
        v.x = fmaxf(Dsm[r * 132 + cb + j + 0] + bv, 0.f);
        v.y = fmaxf(Dsm[r * 132 + cb + j + 1] + bv, 0.f);
        v.z = fmaxf(Dsm[r * 132 + cb + j + 2] + bv, 0.f);
        v.w = fmaxf(Dsm[r * 132 + cb + j + 3] + bv, 0.f);
        *(float4*)(yr + j) = v;
    }
}

// -------- fused occ tail: h2 = relu(Wo2 h1 + b), occ = |Wo3 h2|, q += sums ----
#define W2OFF 0
#define W3OFF 33792
#define H1OFF 51200
#define H2OFF 68096
#define OSMEM 101888
__global__ __launch_bounds__(256)
void occ_tail(const float* __restrict__ h1, const float* __restrict__ wo2,
              const float* __restrict__ bo2, const float* __restrict__ wo3,
              float* __restrict__ occ, float* __restrict__ q)
{
    extern __shared__ __align__(16) char smem[];
    float* W2s = (float*)(smem + W2OFF);   // [64][132]
    float* W3s = (float*)(smem + W3OFF);   // [64][68]
    float* H1s = (float*)(smem + H1OFF);   // [32][132]
    float* H2s = (float*)(smem + H2OFF);   // [64][132]

    const int t = threadIdx.x;
    const int s0 = blockIdx.x * 128, b = blockIdx.z;
    const int tm = t >> 4, tn = t & 15;    // 16 x 16

#pragma unroll
    for (int i = 0; i < 8; ++i) {
        const int vid = t + i * 256;
        const int r = vid >> 5, c4 = (vid & 31) * 4;
        *(float4*)&W2s[r * 132 + c4] = *(const float4*)(wo2 + r * 128 + c4);
    }
#pragma unroll
    for (int i = 0; i < 4; ++i) {
        const int vid = t + i * 256;
        const int r = vid >> 4, c4 = (vid & 15) * 4;
        *(float4*)&W3s[r * 68 + c4] = *(const float4*)(wo3 + r * 64 + c4);
    }

    float acc1[4][8];
#pragma unroll
    for (int i = 0; i < 4; ++i)
#pragma unroll
        for (int j = 0; j < 8; ++j) acc1[i][j] = 0.f;

    for (int c0 = 0; c0 < 128; c0 += 32) {
        __syncthreads();
#pragma unroll
        for (int i = 0; i < 4; ++i) {
            const int vid = t + i * 256;
            const int r = vid >> 5, sc = (vid & 31) * 4;
            *(float4*)&H1s[r * 132 + sc] =
                *(const float4*)(h1 + ((long)b * 128 + c0 + r) * SS + s0 + sc);
        }
        __syncthreads();
#pragma unroll
        for (int kk = 0; kk < 32; ++kk) {
            float a[4], v[8];
#pragma unroll
            for (int i = 0; i < 4; ++i) a[i] = W2s[(tm * 4 + i) * 132 + c0 + kk];
#pragma unroll
            for (int j = 0; j < 8; ++j) v[j] = H1s[kk * 132 + tn * 8 + j];
#pragma unroll
            for (int i = 0; i < 4; ++i)
#pragma unroll
                for (int j = 0; j < 8; ++j) acc1[i][j] += a[i] * v[j];
        }
    }
    __syncthreads();
#pragma unroll
    for (int i = 0; i < 4; ++i) {
        const float bv = bo2[tm * 4 + i];
#pragma unroll
        for (int j = 0; j < 8; ++j)
            H2s[(tm * 4 + i) * 132 + tn * 8 + j] = fmaxf(acc1[i][j] + bv, 0.f);
    }
    __syncthreads();

    float acc2[4][8];
#pragma unroll
    for (int i = 0; i < 4; ++i)
#pragma unroll
        for (int j = 0; j < 8; ++j) acc2[i][j] = 0.f;
#pragma unroll
    for (int kk = 0; kk < 64; ++kk) {
        float a[4], v[8];
#pragma unroll
        for (int i = 0; i < 4; ++i) a[i] = W3s[(tm * 4 + i) * 68 + kk];
#pragma unroll
        for (int j = 0; j < 8; ++j) v[j] = H2s[kk * 132 + tn * 8 + j];
#pragma unroll
        for (int i = 0; i < 4; ++i)
#pragma unroll
            for (int j = 0; j < 8; ++j) acc2[i][j] += a[i] * v[j];
    }
#pragma unroll
    for (int i = 0; i < 4; ++i) {
        const int o = tm * 4 + i;
        float4 v0, v1;
        float* dst = occ + ((long)b * COUT + o) * SS + s0 + tn * 8;
        v0.x = fabsf(acc2[i][0]); v0.y = fabsf(acc2[i][1]);
        v0.z = fabsf(acc2[i][2]); v0.w = fabsf(acc2[i][3]);
        v1.x = fabsf(acc2[i][4]); v1.y = fabsf(acc2[i][5]);
        v1.z = fabsf(acc2[i][6]); v1.w = fabsf(acc2[i][7]);
        *(float4*)dst = v0;
        *(float4*)(dst + 4) = v1;
        float qp = v0.x + v0.y + v0.z + v0.w + v1.x + v1.y + v1.z + v1.w;
#pragma unroll
        for (int off = 8; off > 0; off >>= 1)
            qp += __shfl_xor_sync(0xffffffff, qp, off);
        if (tn == 0) atomicAdd(&q[b * COUT + o], qp * (1.0f / (float)SS));
    }
}

// ------ P[b,o,k] = (1/S) sum_s occ[b,o,s] * y1[b,k,s]  (R5 64-tile version) --
__global__ __launch_bounds__(256)
void pool_contract(const float* __restrict__ Occ, const float* __restrict__ Y1,
                   float* __restrict__ P)
{
    const int S = SS;
    const int bz = blockIdx.z;
    const int b  = bz / NSPLIT;
    const int sp = bz % NSPLIT;
    const int chunk = S / NSPLIT;
    const int sbeg  = sp * chunk;

    const float* Ab = Occ + (long)b * COUT * S;
    const float* Fb = Y1  + (long)b * CIN  * S;
    const int n0 = blockIdx.x * 64;

    __shared__ float As[16][64 + 4];
    __shared__ float Bs[16][64 + 4];

    const int t  = threadIdx.x;
    const int tn = t % 16;
    const int tm = t / 16;
    const int lrow = t >> 2;
    const int lk   = (t & 3) * 4;

    float acc[4][4];
#pragma unroll
    for (int i = 0; i < 4; i++)
#pragma unroll
        for (int j = 0; j < 4; j++) acc[i][j] = 0.f;

    for (int s0 = sbeg; s0 < sbeg + chunk; s0 += 16) {
        float4 a4 = *(const float4*)(Ab + (long)lrow * S + s0 + lk);
        As[lk+0][lrow] = a4.x; As[lk+1][lrow] = a4.y;
        As[lk+2][lrow] = a4.z; As[lk+3][lrow] = a4.w;
        float4 f4 = *(const float4*)(Fb + (long)(n0 + lrow) * S + s0 + lk);
        Bs[lk+0][lrow] = f4.x; Bs[lk+1][lrow] = f4.y;
        Bs[lk+2][lrow] = f4.z; Bs[lk+3][lrow] = f4.w;
        __syncthreads();

#pragma unroll
        for (int kk = 0; kk < 16; kk++) {
            float4 av = *(const float4*)&As[kk][tm * 4];
            float4 bv = *(const float4*)&Bs[kk][tn * 4];
            float a[4] = {av.x, av.y, av.z, av.w};
            float c[4] = {bv.x, bv.y, bv.z, bv.w};
#pragma unroll
            for (int i = 0; i < 4; i++)
#pragma unroll
                for (int j = 0; j < 4; j++) acc[i][j] += a[i] * c[j];
        }
        __syncthreads();
    }

    const float scale = 1.0f / (float)S;
#pragma unroll
    for (int i = 0; i < 4; i++)
#pragma unroll
        for (int j = 0; j < 4; j++) {
            const int o = tm * 4 + i;
            const int k = n0 + tn * 4 + j;
            atomicAdd(&P[((long)b * COUT + o) * CIN + k], acc[i][j] * scale);
        }
}

// ------ out[b,o,c] = sum_k P[b,o,k]*W2[c,k] + q[b,o]*b2[c] -------------------
__global__ __launch_bounds__(256)
void fin_gemm(const float* __restrict__ P, const float* __restrict__ q,
              const float* __restrict__ W2, const float* __restrict__ b2,
              float* __restrict__ out)
{
    const int b = blockIdx.z, c0 = blockIdx.x * 64;
    __shared__ float Pt[64][68];
    __shared__ float Wt[64][68];
    const int t = threadIdx.x;
    const int tm = t >> 4, tn = t & 15;

    float acc[4][4];
#pragma unroll
    for (int i = 0; i < 4; i++)
#pragma unroll
        for (int j = 0; j < 4; j++) acc[i][j] = 0.f;

    for (int k0 = 0; k0 < CIN; k0 += 64) {
#pragma unroll
        for (int i = 0; i < 4; ++i) {
            const int r  = (t >> 4) + i * 16;
            const int kc = (t & 15) * 4;
            *(float4*)&Pt[r][kc] = *(const float4*)(P + ((long)b * COUT + r) * CIN + k0 + kc);
            *(float4*)&Wt[r][kc] = *(const float4*)(W2 + (long)(c0 + r) * CIN + k0 + kc);
        }
        __syncthreads();
#pragma unroll
        for (int kk = 0; kk < 64; ++kk) {
            float a[4], w[4];
#pragma unroll
            for (int i = 0; i < 4; ++i) a[i] = Pt[tm * 4 + i][kk];
#pragma unroll
            for (int j = 0; j < 4; ++j) w[j] = Wt[tn * 4 + j][kk];
#pragma unroll
            for (int i = 0; i < 4; ++i)
#pragma unroll
                for (int j = 0; j < 4; ++j) acc[i][j] += a[i] * w[j];
        }
        __syncthreads();
    }

#pragma unroll
    for (int i = 0; i < 4; ++i) {
        const int o = tm * 4 + i;
        const float qv = q[b * COUT + o];
#pragma unroll
        for (int j = 0; j < 4; ++j) {
            const int c = c0 + tn * 4 + j;
            out[((long)b * COUT + o) * CIN + c] = acc[i][j] + qv * b2[c];
        }
    }
}

// -----------------------------------------------------------------------------
extern "C" void kernel_launch(void* const* d_in, const int* in_sizes, int n_in,
                              void* d_out, int out_size)
{
    const float* x      = (const float*)d_in[0];
    const float* w_add1 = (const float*)d_in[1];
    const float* b_add1 = (const float*)d_in[2];
    const float* w_add2 = (const float*)d_in[3];
    const float* b_add2 = (const float*)d_in[4];
    const float* w_occ1 = (const float*)d_in[5];
    const float* b_occ1 = (const float*)d_in[6];
    const float* w_occ2 = (const float*)d_in[7];
    const float* b_occ2 = (const float*)d_in[8];
    const float* w_occ3 = (const float*)d_in[9];
    float* out = (float*)d_out;

    __nv_bfloat16 *xth, *xtl, *wch, *wcl;
    float *y1, *h1, *occ, *P, *q, *bc;
    cudaGetSymbolAddress((void**)&xth, g_xt_hi);
    cudaGetSymbolAddress((void**)&xtl, g_xt_lo);
    cudaGetSymbolAddress((void**)&y1,  g_y1);
    cudaGetSymbolAddress((void**)&h1,  g_h1);
    cudaGetSymbolAddress((void**)&occ, g_occ);
    cudaGetSymbolAddress((void**)&P,   g_P);
    cudaGetSymbolAddress((void**)&q,   g_q);
    cudaGetSymbolAddress((void**)&wch, g_wch);
    cudaGetSymbolAddress((void**)&wcl, g_wcl);
    cudaGetSymbolAddress((void**)&bc,  g_bc);

    cudaFuncSetAttribute(hmma_gemm, cudaFuncAttributeMaxDynamicSharedMemorySize, HSMEM);
    cudaFuncSetAttribute(occ_tail,  cudaFuncAttributeMaxDynamicSharedMemorySize, OSMEM);

    // launches #1-#3 (pre), #4 = hmma_gemm (ncu captures launch #4)
    transpose_split<<<dim3(SS/32, CIN/32, NB), dim3(32, 8)>>>(x, xth, xtl);
    wsplit_all<<<(MTOT*CIN + 255) / 256, 256>>>(w_add1, w_occ1, wch, wcl);
    prep<<<(NB*COUT*CIN + 255) / 256, 256>>>(b_add1, b_occ1, bc, P, q);

    // merged add1 + occ1: rows 0..511 -> y1, rows 512..639 -> h1
    hmma_gemm<<<dim3(SS/128, MTOT/128, NB), 256, HSMEM>>>(wch, wcl, xth, xtl, bc, y1, h1);

    // fused occ tail (occ2 + occ3 + q)
    occ_tail<<<dim3(SS/128, 1, NB), 256, OSMEM>>>(h1, w_occ2, b_occ2, w_occ3, occ, q);

    // P = (1/S) occ . y1^T
    pool_contract<<<dim3(CIN/64, 1, NB * NSPLIT), 256>>>(occ, y1, P);

    // out = P . W2^T + q b2^T
    fin_gemm<<<dim3(CIN/64, 1, NB), 256>>>(P, q, w_add2, b_add2, out);
}